// round 15
// baseline (speedup 1.0000x reference)
#include <cuda_runtime.h>
#include <cuda_fp16.h>
#include <cstdint>

// Problem constants
#define NN   50000
#define EE   800000
#define FE   16
#define RR   4
#define HH   4
#define CC   32
#define HC   128

#define NT   17   // n-tiles in GEMM B: 16 for W (128 cols) + 1 for folded q|k (8 cols)
#define WFSZ (RR * 4 * 4 * NT * 32 * 2)
#define NBLK 196  // ceil(NN/256)

// ---------------- scratch (static device globals; no allocation) ----------------
// POD storage for fp16 xw (NOT __half: class-type device globals can emit
// per-element dynamic init that hangs module load under EAGER loading)
__device__ __align__(16) unsigned short g_xw[RR * NN * HC];  // fp16 bits (51.2MB)
__device__ __align__(16) float g_h[NN * HC];         // layer-1 output (relu)
__device__ __align__(16) float g_qn[RR * NN * HH];   // per-node query logits [r][n][4]
__device__ __align__(16) float g_kn[RR * NN * HH];   // per-node key logits   [r][n][4]
__device__ __align__(16) float4 g_ea1c[EE];          // edge_attr@M1, CSR-permuted
__device__ __align__(16) float4 g_ea3c[EE];          // edge_attr@M3, CSR-permuted
__device__ int   g_deg[NN];
__device__ int   g_bsum[NBLK];
__device__ int   g_boff[NBLK];
__device__ int   g_rowstart[NN + 1];
__device__ int   g_cursor[NN];
__device__ int   g_csr32[EE];                        // (et<<16)|src, sorted by dst
__device__ int   g_pos[EE];                          // edge id -> csr position
__device__ float g_M1[FE * HH];
__device__ float g_M3[FE * HH];
__device__ __align__(16) float g_wqk[2][RR * HC * 8];   // folded (W@q | W@k), per layer slot
__device__ __align__(16) uint32_t g_wf[2][WFSZ];        // B fragments per layer slot

__device__ __forceinline__ uint32_t f2tf32(float f) {
    uint32_t u;
    asm("cvt.rna.tf32.f32 %0, %1;" : "=r"(u) : "f"(f));
    return u;
}

// pack two floats -> fp16x2 bits
__device__ __forceinline__ uint32_t pack_h2(float a, float b) {
    __half2 h = __floats2half2_rn(a, b);
    return *reinterpret_cast<uint32_t*>(&h);
}
// unpack fp16x2 bits -> two floats
__device__ __forceinline__ float2 unpack_h2(uint32_t u) {
    __half2 h = *reinterpret_cast<__half2*>(&u);
    return __half22float2(h);
}

// ---------------- CSR build ----------------
__global__ void k_zero_deg() {
    int i = blockIdx.x * blockDim.x + threadIdx.x;
    if (i < NN) g_deg[i] = 0;
}

__global__ void k_hist(const int* __restrict__ ei) {
    int e = blockIdx.x * blockDim.x + threadIdx.x;
    if (e < EE) atomicAdd(&g_deg[ei[EE + e]], 1);
}

// phase 1: per-block degree sums
__global__ void k_sum() {
    int b = blockIdx.x, t = threadIdx.x;
    int i = b * 256 + t;
    int v = (i < NN) ? g_deg[i] : 0;
#pragma unroll
    for (int off = 16; off; off >>= 1) v += __shfl_xor_sync(0xFFFFFFFF, v, off);
    __shared__ int ws[8];
    if ((t & 31) == 0) ws[t >> 5] = v;
    __syncthreads();
    if (t == 0) {
        int s = 0;
#pragma unroll
        for (int w = 0; w < 8; w++) s += ws[w];
        g_bsum[b] = s;
    }
}

// phase 2: scan 196 block sums (1 block, 256 threads)
__global__ void k_scanb() {
    __shared__ int sm[256];
    int t = threadIdx.x;
    int v = (t < NBLK) ? g_bsum[t] : 0;
    sm[t] = v;
    __syncthreads();
    for (int off = 1; off < 256; off <<= 1) {
        int y = (t >= off) ? sm[t - off] : 0;
        __syncthreads();
        sm[t] += y;
        __syncthreads();
    }
    if (t < NBLK) g_boff[t] = sm[t] - v;     // exclusive
    if (t == 0) g_rowstart[NN] = EE;
}

// phase 3: local scan + block offset -> rowstart / cursor
__global__ void k_rows() {
    __shared__ int wsum[8];
    int b = blockIdx.x, t = threadIdx.x;
    int i = b * 256 + t;
    int lane = t & 31, wid = t >> 5;
    int v = (i < NN) ? g_deg[i] : 0;
    int x = v;
#pragma unroll
    for (int off = 1; off < 32; off <<= 1) {
        int y = __shfl_up_sync(0xFFFFFFFF, x, off);
        if (lane >= off) x += y;
    }
    if (lane == 31) wsum[wid] = x;
    __syncthreads();
    __shared__ int woff[8];
    if (t == 0) {
        int s = 0;
#pragma unroll
        for (int w = 0; w < 8; w++) { woff[w] = s; s += wsum[w]; }
    }
    __syncthreads();
    if (i < NN) {
        int excl = g_boff[b] + woff[wid] + x - v;
        g_rowstart[i] = excl;
        g_cursor[i] = excl;
    }
}

__global__ void k_scatter(const int* __restrict__ ei, const int* __restrict__ etype) {
    int e = blockIdx.x * blockDim.x + threadIdx.x;
    if (e >= EE) return;
    int d = ei[EE + e];
    int s = ei[e];
    int t = etype[e];
    int pos = atomicAdd(&g_cursor[d], 1);
    g_csr32[pos] = (t << 16) | s;
    g_pos[e] = pos;
}

// ---------------- folded q/k: g_wqk[slot][r][f][0:4]=W_r@q, [4:8]=W_r@k ----------------
__global__ void k_wqk(const float* __restrict__ w, const float* __restrict__ q,
                      const float* __restrict__ k, int slot) {
    int idx = blockIdx.x * 256 + threadIdx.x;    // 4096 total
    if (idx >= RR * HC * 8) return;
    int r = idx >> 10;
    int f = (idx >> 3) & 127;
    int o = idx & 7;
    const float* vec = (o < 4) ? q : k;
    int h = o & 3;
    const float* wrow = w + (r << 14) + (f << 7);
    float s = 0.f;
#pragma unroll 8
    for (int c = 0; c < HC; c++) s += wrow[c] * vec[c * 4 + h];
    g_wqk[slot][idx] = s;
}

// ---------------- B fragment pack (W cols 0..127 + folded q|k cols 128..135) ----------------
__global__ void k_wfrag(const float* __restrict__ w, int slot) {
    int idx = blockIdx.x * 256 + threadIdx.x;          // over WFSZ = 69632
    if (idx >= WFSZ) return;
    int b    = idx & 1;
    int lane = (idx >> 1) & 31;
    int rest = idx >> 6;
    int j    = rest % NT;
    rest /= NT;
    int s    = rest & 3;
    int p    = (rest >> 2) & 3;
    int r    = rest >> 4;
    int k = p * 32 + s * 8 + (b ? 4 : 0) + (lane & 3);
    int c = j * 8 + (lane >> 2);
    float val;
    if (j < 16) val = w[((size_t)r << 14) + k * 128 + c];
    else        val = g_wqk[slot][((size_t)r * HC + k) * 8 + (c - 128)];
    g_wf[slot][idx] = f2tf32(val);
}

// ---------------- M = le @ e  (16x4, both layers) ----------------
__global__ void k_M(const float* __restrict__ le1, const float* __restrict__ e1,
                    const float* __restrict__ le3, const float* __restrict__ e3) {
    int t = threadIdx.x;
    if (t < 64) {
        int f = t >> 2, h = t & 3;
        float s = 0.f;
        for (int c = 0; c < HC; c++) s += le1[f * HC + c] * e1[c * HH + h];
        g_M1[t] = s;
    } else if (t < 128) {
        int u = t - 64;
        int f = u >> 2, h = u & 3;
        float s = 0.f;
        for (int c = 0; c < HC; c++) s += le3[f * HC + c] * e3[c * HH + h];
        g_M3[u] = s;
    }
}

// ---------------- ea terms for BOTH layers, written in CSR order ----------------
__global__ void k_eacsr(const float* __restrict__ eattr) {
    __shared__ float sM1[64], sM3[64];
    if (threadIdx.x < 64) sM1[threadIdx.x] = g_M1[threadIdx.x];
    else if (threadIdx.x < 128) sM3[threadIdx.x - 64] = g_M3[threadIdx.x - 64];
    __syncthreads();
    int e = blockIdx.x * 256 + threadIdx.x;
    if (e >= EE) return;
    const float* a = eattr + (size_t)e * FE;
    float r1[4] = {0, 0, 0, 0}, r3[4] = {0, 0, 0, 0};
#pragma unroll
    for (int f4 = 0; f4 < 4; f4++) {
        float4 av = *(const float4*)(a + f4 * 4);
        const float* m1 = &sM1[f4 * 16];
        const float* m3 = &sM3[f4 * 16];
#pragma unroll
        for (int h = 0; h < 4; h++) {
            r1[h] += av.x * m1[h] + av.y * m1[4 + h] + av.z * m1[8 + h] + av.w * m1[12 + h];
            r3[h] += av.x * m3[h] + av.y * m3[4 + h] + av.z * m3[8 + h] + av.w * m3[12 + h];
        }
    }
    int pos = g_pos[e];
    g_ea1c[pos] = make_float4(r1[0], r1[1], r1[2], r1[3]);
    g_ea3c[pos] = make_float4(r3[0], r3[1], r3[2], r3[3]);
}

// ---------------- tensor-core GEMM: [xw(fp16) | qn | kn] = X @ [W | Wq | Wk] ----------------
#define XS_STRIDE 36
__global__ void __launch_bounds__(256) k_gemmt(const float* __restrict__ xin_arg, int layer) {
    __shared__ uint32_t xs[128 * XS_STRIDE];           // 18.4 KB (tf32 bits)
    __shared__ uint32_t ws[4 * NT * 32 * 2];           // 17.4 KB per K-phase
    const float* xin = (layer == 1) ? xin_arg : g_h;
    int slot = layer - 1;
    int r = blockIdx.y;
    int i0 = blockIdx.x * 128;
    int tid = threadIdx.x;
    int lane = tid & 31, wid = tid >> 5;
    int wr = wid * 16;                                  // warp row offset

    float d[NT][4];
#pragma unroll
    for (int j = 0; j < NT; j++) {
        d[j][0] = 0.f; d[j][1] = 0.f; d[j][2] = 0.f; d[j][3] = 0.f;
    }

    const uint32_t* wsrc = g_wf[slot] + (size_t)r * (4 * 4 * NT * 64);

    for (int p = 0; p < 4; p++) {
        __syncthreads();                                // protect prev phase reads
#pragma unroll
        for (int it = 0; it < 4; it++) {
            int q = tid + it * 256;                     // float4 index
            int row = q >> 3, c4 = q & 7;
            float4 v = make_float4(0.f, 0.f, 0.f, 0.f);
            int gr = i0 + row;
            if (gr < NN) v = *(const float4*)(xin + (size_t)gr * 128 + p * 32 + c4 * 4);
            uint32_t* dst = &xs[row * XS_STRIDE + c4 * 4];
            dst[0] = f2tf32(v.x); dst[1] = f2tf32(v.y);
            dst[2] = f2tf32(v.z); dst[3] = f2tf32(v.w);
        }
        // load B fragments for this phase: 4*NT*64 = 4352 uints = 1088 uint4
        const uint4* wsp = (const uint4*)(wsrc + p * (4 * NT * 64));
#pragma unroll
        for (int it = 0; it < 5; it++) {
            int q = tid + it * 256;
            if (q < 4 * NT * 16) ((uint4*)ws)[q] = __ldg(&wsp[q]);
        }
        __syncthreads();

#pragma unroll
        for (int s = 0; s < 4; s++) {
            int arow = wr + (lane >> 2);
            int acol = s * 8 + (lane & 3);
            uint32_t a0 = xs[arow * XS_STRIDE + acol];
            uint32_t a1 = xs[(arow + 8) * XS_STRIDE + acol];
            uint32_t a2 = xs[arow * XS_STRIDE + acol + 4];
            uint32_t a3 = xs[(arow + 8) * XS_STRIDE + acol + 4];
            const uint32_t* wrow = &ws[(s * NT) * 64];
#pragma unroll
            for (int j = 0; j < NT; j++) {
                uint2 bv = *(const uint2*)&wrow[j * 64 + lane * 2];
                asm volatile(
                    "mma.sync.aligned.m16n8k8.row.col.f32.tf32.tf32.f32 "
                    "{%0,%1,%2,%3}, {%4,%5,%6,%7}, {%8,%9}, {%0,%1,%2,%3};"
                    : "+f"(d[j][0]), "+f"(d[j][1]), "+f"(d[j][2]), "+f"(d[j][3])
                    : "r"(a0), "r"(a1), "r"(a2), "r"(a3), "r"(bv.x), "r"(bv.y));
            }
        }
    }

    // store xw tile (tiles 0..15) as fp16 bits
    int row0 = i0 + wr + (lane >> 2);
    int row1 = row0 + 8;
    unsigned short* base = g_xw + (size_t)r * NN * HC;
#pragma unroll
    for (int j = 0; j < 16; j++) {
        int col = j * 8 + (lane & 3) * 2;
        if (row0 < NN)
            *(uint32_t*)&base[(size_t)row0 * 128 + col] = pack_h2(d[j][0], d[j][1]);
        if (row1 < NN)
            *(uint32_t*)&base[(size_t)row1 * 128 + col] = pack_h2(d[j][2], d[j][3]);
    }
    // tile 16 holds qn (cols 0..3) | kn (cols 4..7) per row (fp32)
    {
        int q4 = lane & 3;                               // col pair = 2*q4
        float* dst = (q4 < 2) ? g_qn : g_kn;
        int off = (q4 < 2) ? q4 * 2 : (q4 - 2) * 2;
        if (row0 < NN) *(float2*)&dst[((size_t)r * NN + row0) * 4 + off] = make_float2(d[16][0], d[16][1]);
        if (row1 < NN) *(float2*)&dst[((size_t)r * NN + row1) * 4 + off] = make_float2(d[16][2], d[16][3]);
    }
}

// ---------------- fused softmax + aggregate: warp per dst node ----------------
// Lane owns channels 4*lane..4*lane+3 (head lane>>3): one LDG.64 (4 halves) per edge.
__global__ void k_agg(const float* __restrict__ bias, float* __restrict__ out, int layer) {
    int n = (blockIdx.x * blockDim.x + threadIdx.x) >> 5;
    int lane = threadIdx.x & 31;
    if (n >= NN) return;
    int rs = g_rowstart[n], re = g_rowstart[n + 1];
    int h = lane >> 3;
    const float4* eac = (layer == 1) ? g_ea1c : g_ea3c;

    float4 qi0 = *(const float4*)&g_qn[((size_t)0 * NN + n) * 4];
    float4 qi1 = *(const float4*)&g_qn[((size_t)1 * NN + n) * 4];
    float4 qi2 = *(const float4*)&g_qn[((size_t)2 * NN + n) * 4];
    float4 qi3 = *(const float4*)&g_qn[((size_t)3 * NN + n) * 4];
#define HSEL(v) (h < 2 ? (h == 0 ? (v).x : (v).y) : (h == 2 ? (v).z : (v).w))
    float qs0 = HSEL(qi0), qs1 = HSEL(qi1), qs2 = HSEL(qi2), qs3 = HSEL(qi3);
#define QSEL(et) ((et) < 2 ? ((et) == 0 ? qs0 : qs1) : ((et) == 2 ? qs2 : qs3))

    float s = 0.f;
    float4 acc = make_float4(0.f, 0.f, 0.f, 0.f);

    int e = rs;
    for (; e + 4 <= re; e += 4) {
        int r0 = g_csr32[e], r1 = g_csr32[e + 1], r2 = g_csr32[e + 2], r3 = g_csr32[e + 3];
        float4 e0 = eac[e], e1 = eac[e + 1], e2 = eac[e + 2], e3 = eac[e + 3];
        int t0 = r0 >> 16, t1 = r1 >> 16, t2 = r2 >> 16, t3 = r3 >> 16;
        int s0i = r0 & 0xFFFF, s1i = r1 & 0xFFFF, s2i = r2 & 0xFFFF, s3i = r3 & 0xFFFF;
        float4 kv0 = *((const float4*)g_kn + ((size_t)t0 * NN + s0i));
        float4 kv1 = *((const float4*)g_kn + ((size_t)t1 * NN + s1i));
        float4 kv2 = *((const float4*)g_kn + ((size_t)t2 * NN + s2i));
        float4 kv3 = *((const float4*)g_kn + ((size_t)t3 * NN + s3i));
        uint2 u0 = *((const uint2*)(g_xw + ((size_t)t0 * NN + s0i) * 128) + lane);
        uint2 u1 = *((const uint2*)(g_xw + ((size_t)t1 * NN + s1i) * 128) + lane);
        uint2 u2 = *((const uint2*)(g_xw + ((size_t)t2 * NN + s2i) * 128) + lane);
        uint2 u3 = *((const uint2*)(g_xw + ((size_t)t3 * NN + s3i) * 128) + lane);
        float a0 = QSEL(t0) + HSEL(kv0) + HSEL(e0); a0 = a0 > 0.f ? a0 : 0.2f * a0;
        float a1 = QSEL(t1) + HSEL(kv1) + HSEL(e1); a1 = a1 > 0.f ? a1 : 0.2f * a1;
        float a2 = QSEL(t2) + HSEL(kv2) + HSEL(e2); a2 = a2 > 0.f ? a2 : 0.2f * a2;
        float a3 = QSEL(t3) + HSEL(kv3) + HSEL(e3); a3 = a3 > 0.f ? a3 : 0.2f * a3;
        float ph0 = __expf(a0), ph1 = __expf(a1), ph2 = __expf(a2), ph3 = __expf(a3);
        s += (ph0 + ph1) + (ph2 + ph3);
        float2 f0a = unpack_h2(u0.x), f0b = unpack_h2(u0.y);
        float2 f1a = unpack_h2(u1.x), f1b = unpack_h2(u1.y);
        float2 f2a = unpack_h2(u2.x), f2b = unpack_h2(u2.y);
        float2 f3a = unpack_h2(u3.x), f3b = unpack_h2(u3.y);
        acc.x += ph0 * f0a.x + ph1 * f1a.x + ph2 * f2a.x + ph3 * f3a.x;
        acc.y += ph0 * f0a.y + ph1 * f1a.y + ph2 * f2a.y + ph3 * f3a.y;
        acc.z += ph0 * f0b.x + ph1 * f1b.x + ph2 * f2b.x + ph3 * f3b.x;
        acc.w += ph0 * f0b.y + ph1 * f1b.y + ph2 * f2b.y + ph3 * f3b.y;
    }
    for (; e < re; e++) {
        int r0 = g_csr32[e];
        float4 e0 = eac[e];
        int t0 = r0 >> 16, s0i = r0 & 0xFFFF;
        float4 kv0 = *((const float4*)g_kn + ((size_t)t0 * NN + s0i));
        uint2 u0 = *((const uint2*)(g_xw + ((size_t)t0 * NN + s0i) * 128) + lane);
        float a0 = QSEL(t0) + HSEL(kv0) + HSEL(e0); a0 = a0 > 0.f ? a0 : 0.2f * a0;
        float ph0 = __expf(a0);
        s += ph0;
        float2 f0a = unpack_h2(u0.x), f0b = unpack_h2(u0.y);
        acc.x += ph0 * f0a.x; acc.y += ph0 * f0a.y;
        acc.z += ph0 * f0b.x; acc.w += ph0 * f0b.y;
    }
#undef QSEL
#undef HSEL

    const float EPS = 1e-16f;
    float inv = 1.f / (s + EPS);
    if (layer == 1) {
        float4 b4 = *(const float4*)&bias[lane * 4];
        float v0 = acc.x * inv + b4.x;
        float v1 = acc.y * inv + b4.y;
        float v2 = acc.z * inv + b4.z;
        float v3 = acc.w * inv + b4.w;
        *(float4*)&g_h[(size_t)n * 128 + lane * 4] =
            make_float4(v0 > 0.f ? v0 : 0.f, v1 > 0.f ? v1 : 0.f,
                        v2 > 0.f ? v2 : 0.f, v3 > 0.f ? v3 : 0.f);
    } else {
        float4 v = make_float4(acc.x * inv, acc.y * inv, acc.z * inv, acc.w * inv);
#pragma unroll
        for (int off = 8; off <= 16; off <<= 1) {
            v.x += __shfl_xor_sync(0xFFFFFFFF, v.x, off);
            v.y += __shfl_xor_sync(0xFFFFFFFF, v.y, off);
            v.z += __shfl_xor_sync(0xFFFFFFFF, v.z, off);
            v.w += __shfl_xor_sync(0xFFFFFFFF, v.w, off);
        }
        if (lane < 8) {
            float4 b4 = *(const float4*)&bias[lane * 4];
            *(float4*)&out[(size_t)n * 32 + lane * 4] =
                make_float4(0.25f * v.x + b4.x, 0.25f * v.y + b4.y,
                            0.25f * v.z + b4.z, 0.25f * v.w + b4.w);
        }
    }
}

// ---------------- launch (fork/join over 3 streams; graph-capture safe) ----------------
extern "C" void kernel_launch(void* const* d_in, const int* in_sizes, int n_in,
                              void* d_out, int out_size) {
    const float* x     = (const float*)d_in[0];
    const int*   ei    = (const int*)  d_in[1];
    const float* eattr = (const float*)d_in[2];
    const int*   etype = (const int*)  d_in[3];
    const float* w1  = (const float*)d_in[4];
    const float* q1  = (const float*)d_in[5];
    const float* k1  = (const float*)d_in[6];
    const float* e1  = (const float*)d_in[7];
    const float* le1 = (const float*)d_in[8];
    const float* b1  = (const float*)d_in[9];
    const float* w3  = (const float*)d_in[10];
    const float* q3  = (const float*)d_in[11];
    const float* k3  = (const float*)d_in[12];
    const float* e3  = (const float*)d_in[13];
    const float* le3 = (const float*)d_in[14];
    const float* b3  = (const float*)d_in[15];
    float* out = (float*)d_out;

    const int EB = (EE + 255) / 256;         // 3125
    const int WF_B = (WFSZ + 255) / 256;     // 272
    const dim3 GT((NN + 127) / 128, RR);     // (391, 4)
    const int NAGG = (NN + 7) / 8;

    static cudaStream_t s2 = nullptr, s3 = nullptr;
    static cudaEvent_t evRoot = nullptr, evCSR = nullptr, evW3 = nullptr;
    if (!s2) {
        cudaStreamCreateWithFlags(&s2, cudaStreamNonBlocking);
        cudaStreamCreateWithFlags(&s3, cudaStreamNonBlocking);
        cudaEventCreateWithFlags(&evRoot, cudaEventDisableTiming);
        cudaEventCreateWithFlags(&evCSR, cudaEventDisableTiming);
        cudaEventCreateWithFlags(&evW3, cudaEventDisableTiming);
    }

    // fork
    cudaEventRecord(evRoot, 0);
    cudaStreamWaitEvent(s2, evRoot, 0);
    cudaStreamWaitEvent(s3, evRoot, 0);

    // s2: CSR build chain + M + ea-in-CSR-order (both layers)
    k_zero_deg<<<NBLK, 256, 0, s2>>>();
    k_hist<<<EB, 256, 0, s2>>>(ei);
    k_M<<<1, 128, 0, s2>>>(le1, e1, le3, e3);
    k_sum<<<NBLK, 256, 0, s2>>>();
    k_scanb<<<1, 256, 0, s2>>>();
    k_rows<<<NBLK, 256, 0, s2>>>();
    k_scatter<<<EB, 256, 0, s2>>>(ei, etype);
    k_eacsr<<<EB, 256, 0, s2>>>(eattr);
    cudaEventRecord(evCSR, s2);

    // s3: layer-2 weight prep (slot 1)
    k_wqk<<<16, 256, 0, s3>>>(w3, q3, k3, 1);
    k_wfrag<<<WF_B, 256, 0, s3>>>(w3, 1);
    cudaEventRecord(evW3, s3);

    // stream 0: critical path
    k_wqk<<<16, 256>>>(w1, q1, k1, 0);
    k_wfrag<<<WF_B, 256>>>(w1, 0);
    k_gemmt<<<GT, 256>>>(x, 1);
    cudaStreamWaitEvent(0, evCSR, 0);                 // join CSR + ea
    k_agg<<<NAGG, 256>>>(b1, out, 1);
    cudaStreamWaitEvent(0, evW3, 0);                  // join layer-2 weights
    k_gemmt<<<GT, 256>>>(x, 2);
    k_agg<<<NAGG, 256>>>(b3, out, 2);
}

// round 16
// speedup vs baseline: 1.3572x; 1.3572x over previous
#include <cuda_runtime.h>
#include <cstdint>

// Problem constants
#define NN   50000
#define EE   800000
#define FE   16
#define RR   4
#define HH   4
#define CC   32
#define HC   128

#define NT   17   // n-tiles in GEMM B: 16 for W (128 cols) + 1 for folded q|k (8 cols)
#define WFSZ (RR * 4 * 4 * NT * 32 * 2)
#define NBLK 196  // ceil(NN/256)

// ---------------- scratch (static device globals; no allocation) ----------------
__device__ __align__(16) float g_xw[RR * NN * HC];   // per-relation projections (102.4MB)
__device__ __align__(16) float g_h[NN * HC];         // layer-1 output (relu)
__device__ __align__(16) float g_qn[RR * NN * HH];   // per-node query logits [r][n][4]
__device__ __align__(16) float g_kn[RR * NN * HH];   // per-node key logits   [r][n][4]
__device__ __align__(16) float4 g_pp[EE];            // per-edge probs, CSR order
__device__ __align__(16) float4 g_ea1c[EE];          // edge_attr@M1, CSR order
__device__ __align__(16) float4 g_ea3c[EE];          // edge_attr@M3, CSR order
__device__ int   g_deg[NN];
__device__ int   g_bsum[NBLK];
__device__ int   g_boff[NBLK];
__device__ int   g_rowstart[NN + 1];
__device__ int   g_cursor[NN];
__device__ int   g_csr32[EE];                        // (et<<16)|src, sorted by dst
__device__ unsigned short g_csrdst[EE];              // dst per csr position
__device__ int   g_pos[EE];                          // edge id -> csr position
__device__ float g_M1[FE * HH];
__device__ float g_M3[FE * HH];
__device__ __align__(16) float g_wqk[2][RR * HC * 8];   // folded (W@q | W@k), per layer slot
__device__ __align__(16) uint32_t g_wf[2][WFSZ];        // B fragments per layer slot

__device__ __forceinline__ uint32_t f2tf32(float f) {
    uint32_t u;
    asm("cvt.rna.tf32.f32 %0, %1;" : "=r"(u) : "f"(f));
    return u;
}

// ---------------- CSR build ----------------
__global__ void k_zero_deg() {
    int i = blockIdx.x * blockDim.x + threadIdx.x;
    if (i < NN) g_deg[i] = 0;
}

__global__ void k_hist(const int* __restrict__ ei) {
    int e = blockIdx.x * blockDim.x + threadIdx.x;
    if (e < EE) atomicAdd(&g_deg[ei[EE + e]], 1);
}

// phase 1: per-block degree sums
__global__ void k_sum() {
    int b = blockIdx.x, t = threadIdx.x;
    int i = b * 256 + t;
    int v = (i < NN) ? g_deg[i] : 0;
#pragma unroll
    for (int off = 16; off; off >>= 1) v += __shfl_xor_sync(0xFFFFFFFF, v, off);
    __shared__ int ws[8];
    if ((t & 31) == 0) ws[t >> 5] = v;
    __syncthreads();
    if (t == 0) {
        int s = 0;
#pragma unroll
        for (int w = 0; w < 8; w++) s += ws[w];
        g_bsum[b] = s;
    }
}

// phase 2: scan 196 block sums (1 block, 256 threads)
__global__ void k_scanb() {
    __shared__ int sm[256];
    int t = threadIdx.x;
    int v = (t < NBLK) ? g_bsum[t] : 0;
    sm[t] = v;
    __syncthreads();
    for (int off = 1; off < 256; off <<= 1) {
        int y = (t >= off) ? sm[t - off] : 0;
        __syncthreads();
        sm[t] += y;
        __syncthreads();
    }
    if (t < NBLK) g_boff[t] = sm[t] - v;     // exclusive
    if (t == 0) g_rowstart[NN] = EE;
}

// phase 3: local scan + block offset -> rowstart / cursor
__global__ void k_rows() {
    __shared__ int wsum[8];
    int b = blockIdx.x, t = threadIdx.x;
    int i = b * 256 + t;
    int lane = t & 31, wid = t >> 5;
    int v = (i < NN) ? g_deg[i] : 0;
    int x = v;
#pragma unroll
    for (int off = 1; off < 32; off <<= 1) {
        int y = __shfl_up_sync(0xFFFFFFFF, x, off);
        if (lane >= off) x += y;
    }
    if (lane == 31) wsum[wid] = x;
    __syncthreads();
    __shared__ int woff[8];
    if (t == 0) {
        int s = 0;
#pragma unroll
        for (int w = 0; w < 8; w++) { woff[w] = s; s += wsum[w]; }
    }
    __syncthreads();
    if (i < NN) {
        int excl = g_boff[b] + woff[wid] + x - v;
        g_rowstart[i] = excl;
        g_cursor[i] = excl;
    }
}

__global__ void k_scatter(const int* __restrict__ ei, const int* __restrict__ etype) {
    int e = blockIdx.x * blockDim.x + threadIdx.x;
    if (e >= EE) return;
    int d = ei[EE + e];
    int s = ei[e];
    int t = etype[e];
    int pos = atomicAdd(&g_cursor[d], 1);
    g_csr32[pos] = (t << 16) | s;
    g_csrdst[pos] = (unsigned short)d;
    g_pos[e] = pos;
}

// ---------------- folded q/k: g_wqk[slot][r][f][0:4]=W_r@q, [4:8]=W_r@k ----------------
__global__ void k_wqk(const float* __restrict__ w, const float* __restrict__ q,
                      const float* __restrict__ k, int slot) {
    int idx = blockIdx.x * 256 + threadIdx.x;    // 4096 total
    if (idx >= RR * HC * 8) return;
    int r = idx >> 10;
    int f = (idx >> 3) & 127;
    int o = idx & 7;
    const float* vec = (o < 4) ? q : k;
    int h = o & 3;
    const float* wrow = w + (r << 14) + (f << 7);
    float s = 0.f;
#pragma unroll 8
    for (int c = 0; c < HC; c++) s += wrow[c] * vec[c * 4 + h];
    g_wqk[slot][idx] = s;
}

// ---------------- B fragment pack (W cols 0..127 + folded q|k cols 128..135) ----------------
__global__ void k_wfrag(const float* __restrict__ w, int slot) {
    int idx = blockIdx.x * 256 + threadIdx.x;          // over WFSZ = 69632
    if (idx >= WFSZ) return;
    int b    = idx & 1;
    int lane = (idx >> 1) & 31;
    int rest = idx >> 6;
    int j    = rest % NT;
    rest /= NT;
    int s    = rest & 3;
    int p    = (rest >> 2) & 3;
    int r    = rest >> 4;
    int k = p * 32 + s * 8 + (b ? 4 : 0) + (lane & 3);
    int c = j * 8 + (lane >> 2);
    float val;
    if (j < 16) val = w[((size_t)r << 14) + k * 128 + c];
    else        val = g_wqk[slot][((size_t)r * HC + k) * 8 + (c - 128)];
    g_wf[slot][idx] = f2tf32(val);
}

// ---------------- M = le @ e  (16x4, both layers) ----------------
__global__ void k_M(const float* __restrict__ le1, const float* __restrict__ e1,
                    const float* __restrict__ le3, const float* __restrict__ e3) {
    int t = threadIdx.x;
    if (t < 64) {
        int f = t >> 2, h = t & 3;
        float s = 0.f;
        for (int c = 0; c < HC; c++) s += le1[f * HC + c] * e1[c * HH + h];
        g_M1[t] = s;
    } else if (t < 128) {
        int u = t - 64;
        int f = u >> 2, h = u & 3;
        float s = 0.f;
        for (int c = 0; c < HC; c++) s += le3[f * HC + c] * e3[c * HH + h];
        g_M3[u] = s;
    }
}

// ---------------- ea terms for BOTH layers, written in CSR order (off critical path) ----------------
__global__ void k_eacsr(const float* __restrict__ eattr) {
    __shared__ float sM1[64], sM3[64];
    if (threadIdx.x < 64) sM1[threadIdx.x] = g_M1[threadIdx.x];
    else if (threadIdx.x < 128) sM3[threadIdx.x - 64] = g_M3[threadIdx.x - 64];
    __syncthreads();
    int e = blockIdx.x * 256 + threadIdx.x;
    if (e >= EE) return;
    const float* a = eattr + (size_t)e * FE;
    float r1[4] = {0, 0, 0, 0}, r3[4] = {0, 0, 0, 0};
#pragma unroll
    for (int f4 = 0; f4 < 4; f4++) {
        float4 av = *(const float4*)(a + f4 * 4);
        const float* m1 = &sM1[f4 * 16];
        const float* m3 = &sM3[f4 * 16];
#pragma unroll
        for (int h = 0; h < 4; h++) {
            r1[h] += av.x * m1[h] + av.y * m1[4 + h] + av.z * m1[8 + h] + av.w * m1[12 + h];
            r3[h] += av.x * m3[h] + av.y * m3[4 + h] + av.z * m3[8 + h] + av.w * m3[12 + h];
        }
    }
    int pos = g_pos[e];
    g_ea1c[pos] = make_float4(r1[0], r1[1], r1[2], r1[3]);
    g_ea3c[pos] = make_float4(r3[0], r3[1], r3[2], r3[3]);
}

// ---------------- tensor-core GEMM: [xw | qn | kn] = X @ [W | Wq | Wk] ----------------
#define XS_STRIDE 36
__global__ void __launch_bounds__(256) k_gemmt(const float* __restrict__ xin_arg, int layer) {
    __shared__ uint32_t xs[128 * XS_STRIDE];           // 18.4 KB (tf32 bits)
    __shared__ uint32_t ws[4 * NT * 32 * 2];           // 17.4 KB per K-phase
    const float* xin = (layer == 1) ? xin_arg : g_h;
    int slot = layer - 1;
    int r = blockIdx.y;
    int i0 = blockIdx.x * 128;
    int tid = threadIdx.x;
    int lane = tid & 31, wid = tid >> 5;
    int wr = wid * 16;                                  // warp row offset

    float d[NT][4];
#pragma unroll
    for (int j = 0; j < NT; j++) {
        d[j][0] = 0.f; d[j][1] = 0.f; d[j][2] = 0.f; d[j][3] = 0.f;
    }

    const uint32_t* wsrc = g_wf[slot] + (size_t)r * (4 * 4 * NT * 64);

    for (int p = 0; p < 4; p++) {
        __syncthreads();                                // protect prev phase reads
#pragma unroll
        for (int it = 0; it < 4; it++) {
            int q = tid + it * 256;                     // float4 index
            int row = q >> 3, c4 = q & 7;
            float4 v = make_float4(0.f, 0.f, 0.f, 0.f);
            int gr = i0 + row;
            if (gr < NN) v = *(const float4*)(xin + (size_t)gr * 128 + p * 32 + c4 * 4);
            uint32_t* dst = &xs[row * XS_STRIDE + c4 * 4];
            dst[0] = f2tf32(v.x); dst[1] = f2tf32(v.y);
            dst[2] = f2tf32(v.z); dst[3] = f2tf32(v.w);
        }
        // load B fragments for this phase: 4*NT*64 = 4352 uints = 1088 uint4
        const uint4* wsp = (const uint4*)(wsrc + p * (4 * NT * 64));
#pragma unroll
        for (int it = 0; it < 5; it++) {
            int q = tid + it * 256;
            if (q < 4 * NT * 16) ((uint4*)ws)[q] = __ldg(&wsp[q]);
        }
        __syncthreads();

#pragma unroll
        for (int s = 0; s < 4; s++) {
            int arow = wr + (lane >> 2);
            int acol = s * 8 + (lane & 3);
            uint32_t a0 = xs[arow * XS_STRIDE + acol];
            uint32_t a1 = xs[(arow + 8) * XS_STRIDE + acol];
            uint32_t a2 = xs[arow * XS_STRIDE + acol + 4];
            uint32_t a3 = xs[(arow + 8) * XS_STRIDE + acol + 4];
            const uint32_t* wrow = &ws[(s * NT) * 64];
#pragma unroll
            for (int j = 0; j < NT; j++) {
                uint2 bv = *(const uint2*)&wrow[j * 64 + lane * 2];
                asm volatile(
                    "mma.sync.aligned.m16n8k8.row.col.f32.tf32.tf32.f32 "
                    "{%0,%1,%2,%3}, {%4,%5,%6,%7}, {%8,%9}, {%0,%1,%2,%3};"
                    : "+f"(d[j][0]), "+f"(d[j][1]), "+f"(d[j][2]), "+f"(d[j][3])
                    : "r"(a0), "r"(a1), "r"(a2), "r"(a3), "r"(bv.x), "r"(bv.y));
            }
        }
    }

    // store xw tile (tiles 0..15), fp32
    int row0 = i0 + wr + (lane >> 2);
    int row1 = row0 + 8;
    float* base = g_xw + (size_t)r * NN * HC;
#pragma unroll
    for (int j = 0; j < 16; j++) {
        int col = j * 8 + (lane & 3) * 2;
        if (row0 < NN) *(float2*)&base[(size_t)row0 * 128 + col] = make_float2(d[j][0], d[j][1]);
        if (row1 < NN) *(float2*)&base[(size_t)row1 * 128 + col] = make_float2(d[j][2], d[j][3]);
    }
    // tile 16 holds qn (cols 0..3) | kn (cols 4..7) per row
    {
        int q4 = lane & 3;                               // col pair = 2*q4
        float* dst = (q4 < 2) ? g_qn : g_kn;
        int off = (q4 < 2) ? q4 * 2 : (q4 - 2) * 2;
        if (row0 < NN) *(float2*)&dst[((size_t)r * NN + row0) * 4 + off] = make_float2(d[16][0], d[16][1]);
        if (row1 < NN) *(float2*)&dst[((size_t)r * NN + row1) * 4 + off] = make_float2(d[16][2], d[16][3]);
    }
}

// ---------------- per-edge probs, CSR-position parallel ----------------
// All streams coalesced except the two 16B qn/kn gathers.
__global__ void k_pc(int layer) {
    int pos = blockIdx.x * 256 + threadIdx.x;
    if (pos >= EE) return;
    int rec = g_csr32[pos];
    int t = rec >> 16, src = rec & 0xFFFF;
    int dst = g_csrdst[pos];
    float4 qv = *(const float4*)&g_qn[((size_t)t * NN + dst) * 4];
    float4 kv = *(const float4*)&g_kn[((size_t)t * NN + src) * 4];
    float4 ev = (layer == 1) ? g_ea1c[pos] : g_ea3c[pos];
    float a0 = qv.x + kv.x + ev.x; a0 = a0 > 0.f ? a0 : 0.2f * a0;
    float a1 = qv.y + kv.y + ev.y; a1 = a1 > 0.f ? a1 : 0.2f * a1;
    float a2 = qv.z + kv.z + ev.z; a2 = a2 > 0.f ? a2 : 0.2f * a2;
    float a3 = qv.w + kv.w + ev.w; a3 = a3 > 0.f ? a3 : 0.2f * a3;
    g_pp[pos] = make_float4(__expf(a0), __expf(a1), __expf(a2), __expf(a3));
}

// ---------------- softmax-normalize + aggregate: warp per dst node ----------------
// Lane owns channels 4*lane..4*lane+3 (head lane>>3): one LDG.128 per edge.
__global__ void k_agg(const float* __restrict__ bias, float* __restrict__ out, int layer) {
    int n = (blockIdx.x * blockDim.x + threadIdx.x) >> 5;
    int lane = threadIdx.x & 31;
    if (n >= NN) return;
    int rs = g_rowstart[n], re = g_rowstart[n + 1];
    int h = lane >> 3;

    float s = 0.f;
    float4 acc = make_float4(0.f, 0.f, 0.f, 0.f);

    int e = rs;
    for (; e + 4 <= re; e += 4) {
        int r0 = g_csr32[e], r1 = g_csr32[e + 1], r2 = g_csr32[e + 2], r3 = g_csr32[e + 3];
        float4 p0 = g_pp[e], p1 = g_pp[e + 1], p2 = g_pp[e + 2], p3 = g_pp[e + 3];
        const float4* x0 = (const float4*)(g_xw + ((size_t)(r0 >> 16) * NN + (r0 & 0xFFFF)) * 128) + lane;
        const float4* x1 = (const float4*)(g_xw + ((size_t)(r1 >> 16) * NN + (r1 & 0xFFFF)) * 128) + lane;
        const float4* x2 = (const float4*)(g_xw + ((size_t)(r2 >> 16) * NN + (r2 & 0xFFFF)) * 128) + lane;
        const float4* x3 = (const float4*)(g_xw + ((size_t)(r3 >> 16) * NN + (r3 & 0xFFFF)) * 128) + lane;
        float4 v0 = *x0, v1 = *x1, v2 = *x2, v3 = *x3;
        float ph0 = h < 2 ? (h == 0 ? p0.x : p0.y) : (h == 2 ? p0.z : p0.w);
        float ph1 = h < 2 ? (h == 0 ? p1.x : p1.y) : (h == 2 ? p1.z : p1.w);
        float ph2 = h < 2 ? (h == 0 ? p2.x : p2.y) : (h == 2 ? p2.z : p2.w);
        float ph3 = h < 2 ? (h == 0 ? p3.x : p3.y) : (h == 2 ? p3.z : p3.w);
        s += (ph0 + ph1) + (ph2 + ph3);
        acc.x += ph0 * v0.x + ph1 * v1.x + ph2 * v2.x + ph3 * v3.x;
        acc.y += ph0 * v0.y + ph1 * v1.y + ph2 * v2.y + ph3 * v3.y;
        acc.z += ph0 * v0.z + ph1 * v1.z + ph2 * v2.z + ph3 * v3.z;
        acc.w += ph0 * v0.w + ph1 * v1.w + ph2 * v2.w + ph3 * v3.w;
    }
    for (; e < re; e++) {
        int r0 = g_csr32[e];
        float4 p0 = g_pp[e];
        const float4* x0 = (const float4*)(g_xw + ((size_t)(r0 >> 16) * NN + (r0 & 0xFFFF)) * 128) + lane;
        float4 v0 = *x0;
        float ph0 = h < 2 ? (h == 0 ? p0.x : p0.y) : (h == 2 ? p0.z : p0.w);
        s += ph0;
        acc.x += ph0 * v0.x; acc.y += ph0 * v0.y;
        acc.z += ph0 * v0.z; acc.w += ph0 * v0.w;
    }

    const float EPS = 1e-16f;
    float inv = 1.f / (s + EPS);
    if (layer == 1) {
        float4 b4 = *(const float4*)&bias[lane * 4];
        float v0 = acc.x * inv + b4.x;
        float v1 = acc.y * inv + b4.y;
        float v2 = acc.z * inv + b4.z;
        float v3 = acc.w * inv + b4.w;
        *(float4*)&g_h[(size_t)n * 128 + lane * 4] =
            make_float4(v0 > 0.f ? v0 : 0.f, v1 > 0.f ? v1 : 0.f,
                        v2 > 0.f ? v2 : 0.f, v3 > 0.f ? v3 : 0.f);
    } else {
        float4 v = make_float4(acc.x * inv, acc.y * inv, acc.z * inv, acc.w * inv);
#pragma unroll
        for (int off = 8; off <= 16; off <<= 1) {
            v.x += __shfl_xor_sync(0xFFFFFFFF, v.x, off);
            v.y += __shfl_xor_sync(0xFFFFFFFF, v.y, off);
            v.z += __shfl_xor_sync(0xFFFFFFFF, v.z, off);
            v.w += __shfl_xor_sync(0xFFFFFFFF, v.w, off);
        }
        if (lane < 8) {
            float4 b4 = *(const float4*)&bias[lane * 4];
            *(float4*)&out[(size_t)n * 32 + lane * 4] =
                make_float4(0.25f * v.x + b4.x, 0.25f * v.y + b4.y,
                            0.25f * v.z + b4.z, 0.25f * v.w + b4.w);
        }
    }
}

// ---------------- launch (fork/join over 3 streams; graph-capture safe) ----------------
extern "C" void kernel_launch(void* const* d_in, const int* in_sizes, int n_in,
                              void* d_out, int out_size) {
    const float* x     = (const float*)d_in[0];
    const int*   ei    = (const int*)  d_in[1];
    const float* eattr = (const float*)d_in[2];
    const int*   etype = (const int*)  d_in[3];
    const float* w1  = (const float*)d_in[4];
    const float* q1  = (const float*)d_in[5];
    const float* k1  = (const float*)d_in[6];
    const float* e1  = (const float*)d_in[7];
    const float* le1 = (const float*)d_in[8];
    const float* b1  = (const float*)d_in[9];
    const float* w3  = (const float*)d_in[10];
    const float* q3  = (const float*)d_in[11];
    const float* k3  = (const float*)d_in[12];
    const float* e3  = (const float*)d_in[13];
    const float* le3 = (const float*)d_in[14];
    const float* b3  = (const float*)d_in[15];
    float* out = (float*)d_out;

    const int EB = (EE + 255) / 256;         // 3125
    const int WF_B = (WFSZ + 255) / 256;     // 272
    const dim3 GT((NN + 127) / 128, RR);     // (391, 4)
    const int NAGG = (NN + 7) / 8;

    static cudaStream_t s2 = nullptr, s3 = nullptr;
    static cudaEvent_t evRoot = nullptr, evCSR = nullptr, evW3 = nullptr;
    if (!s2) {
        cudaStreamCreateWithFlags(&s2, cudaStreamNonBlocking);
        cudaStreamCreateWithFlags(&s3, cudaStreamNonBlocking);
        cudaEventCreateWithFlags(&evRoot, cudaEventDisableTiming);
        cudaEventCreateWithFlags(&evCSR, cudaEventDisableTiming);
        cudaEventCreateWithFlags(&evW3, cudaEventDisableTiming);
    }

    // fork
    cudaEventRecord(evRoot, 0);
    cudaStreamWaitEvent(s2, evRoot, 0);
    cudaStreamWaitEvent(s3, evRoot, 0);

    // s2: CSR build chain + M + ea-in-CSR-order (both layers)
    k_zero_deg<<<NBLK, 256, 0, s2>>>();
    k_hist<<<EB, 256, 0, s2>>>(ei);
    k_M<<<1, 128, 0, s2>>>(le1, e1, le3, e3);
    k_sum<<<NBLK, 256, 0, s2>>>();
    k_scanb<<<1, 256, 0, s2>>>();
    k_rows<<<NBLK, 256, 0, s2>>>();
    k_scatter<<<EB, 256, 0, s2>>>(ei, etype);
    k_eacsr<<<EB, 256, 0, s2>>>(eattr);
    cudaEventRecord(evCSR, s2);

    // s3: layer-2 weight prep (slot 1)
    k_wqk<<<16, 256, 0, s3>>>(w3, q3, k3, 1);
    k_wfrag<<<WF_B, 256, 0, s3>>>(w3, 1);
    cudaEventRecord(evW3, s3);

    // stream 0: critical path
    k_wqk<<<16, 256>>>(w1, q1, k1, 0);
    k_wfrag<<<WF_B, 256>>>(w1, 0);
    k_gemmt<<<GT, 256>>>(x, 1);
    cudaStreamWaitEvent(0, evCSR, 0);                 // join CSR + ea
    k_pc<<<EB, 256>>>(1);
    k_agg<<<NAGG, 256>>>(b1, out, 1);
    cudaStreamWaitEvent(0, evW3, 0);                  // join layer-2 weights
    k_gemmt<<<GT, 256>>>(x, 2);
    k_pc<<<EB, 256>>>(2);
    k_agg<<<NAGG, 256>>>(b3, out, 2);
}